// round 13
// baseline (speedup 1.0000x reference)
#include <cuda_runtime.h>
#include <cuda_bf16.h>
#include <math.h>
#include <stdint.h>

// BootstrappedBCEWithLogitsLoss: mean of top-25% per-row BCE losses.
// B=64 rows of HW=262144 pixels; K = 65536 per row.
//
//  k_sample (1024 thr): zero scratch + per-row 16384-pixel sample ->
//            4096-bin smem histogram -> conservative bracket [Tlo,Thi].
//  k_main  (256 thr, 16 blocks/row): PER-WARP cp.async rings. Each warp owns
//            an 8-stage x 1KB smem ring (stage = 128px: 16B X + 16B Y per
//            lane), commit_group per stage, wait_group<6> -> oldest stage
//            ready. No mbarriers, no __syncthreads, no thread-0 issue
//            serialization -> ~150KB/SM continuously in flight.
//            loss >= Thi: exact branchless sum/count.
//            loss in [Tlo,Thi): 512-bin smem histogram (rare).
//            Last block per row finalizes via parallel suffix scan.

#define NB 64
#define HW 262144
#define TOPK 65536
#define HB1 4096
#define BINS2 512
#define BLKROW 16            // blocks per row in k_main
#define WARPS 8
#define WPIX 2048            // pixels per warp (16384 per block / 8)
#define STAGE_PIX 128        // pixels per stage per warp
#define DSTG 8               // ring depth (stages)
#define NIT (WPIX / STAGE_PIX)          // 16 iterations
#define RING_FLOATS (DSTG * 2 * STAGE_PIX)  // 2048 floats per warp
#define DSMEM (WARPS * RING_FLOATS * 4)     // 64 KB
#define RANK_HI 3604   // 0.88 * 4096  (~9 sigma above top-quartile rank)
#define RANK_LO 4588   // 1.12 * 4096

__device__ float g_Tlo[NB];
__device__ float g_Thi[NB];
__device__ float g_Shi[NB];
__device__ int   g_Chi[NB];
__device__ int   g_cnt2[NB][BINS2];
__device__ unsigned int g_done[NB];

__device__ __forceinline__ float bce(float x, float y) {
    return fmaxf(x, 0.0f) - x * y + __logf(1.0f + __expf(-fabsf(x)));
}

__device__ __forceinline__ uint32_t smem_u32(const void* p) {
    return (uint32_t)__cvta_generic_to_shared(p);
}

#define CP_ASYNC16(saddr, gptr) \
    asm volatile("cp.async.cg.shared.global [%0], [%1], 16;" \
                 :: "r"(saddr), "l"(gptr) : "memory")
#define CP_COMMIT() asm volatile("cp.async.commit_group;" ::: "memory")
#define CP_WAIT6()  asm volatile("cp.async.wait_group 6;" ::: "memory")

// ---------------------------------------------- K1: zero scratch + sample
__global__ void __launch_bounds__(1024) k_sample(const float4* __restrict__ X,
                                                 const float4* __restrict__ Y,
                                                 float* out) {
    __shared__ int hist[HB1];
    __shared__ int csum[256];
    __shared__ int suffix[256];
    __shared__ int wsum[8];
    const int tid = threadIdx.x;
    const int row = blockIdx.x;

    if (tid < BINS2) g_cnt2[row][tid] = 0;
    if (tid == 0) {
        g_Chi[row] = 0;
        g_Shi[row] = 0.0f;
        g_done[row] = 0;
        if (row == 0) out[0] = 0.0f;
    }

    for (int i = tid; i < HB1; i += 1024) hist[i] = 0;
    __syncthreads();

    size_t base = (size_t)row * (HW / 4);
    {
        float4 xv[4], yv[4];
#pragma unroll
        for (int k = 0; k < 4; ++k) {
            int i = k * 1024 + tid;
            xv[k] = X[base + i];
            yv[k] = Y[base + i];
        }
#pragma unroll
        for (int k = 0; k < 4; ++k) {
            float L0 = bce(xv[k].x, yv[k].x);
            float L1 = bce(xv[k].y, yv[k].y);
            float L2 = bce(xv[k].z, yv[k].z);
            float L3 = bce(xv[k].w, yv[k].w);
            atomicAdd(&hist[min(HB1 - 1, max(0, (int)(L0 * 256.0f)))], 1);
            atomicAdd(&hist[min(HB1 - 1, max(0, (int)(L1 * 256.0f)))], 1);
            atomicAdd(&hist[min(HB1 - 1, max(0, (int)(L2 * 256.0f)))], 1);
            atomicAdd(&hist[min(HB1 - 1, max(0, (int)(L3 * 256.0f)))], 1);
        }
    }
    __syncthreads();

    const int b0 = tid * (HB1 / 256);  // only valid for tid<256
    if (tid < 256) {
        int lt = 0;
#pragma unroll
        for (int b = b0; b < b0 + 16; ++b) lt += hist[b];
        csum[tid] = lt;
    }
    __syncthreads();

    if (tid < 256) {
        const int lane = tid & 31, wid = tid >> 5;
        int v = csum[255 - tid];
        int inc = v;
#pragma unroll
        for (int o = 1; o < 32; o <<= 1) {
            int u = __shfl_up_sync(0xffffffffu, inc, o);
            if (lane >= o) inc += u;
        }
        if (lane == 31) wsum[wid] = inc;
        csum[255 - tid] = inc - v;
    }
    __syncthreads();
    if (tid < 256) {
        const int wid = tid >> 5;
        int off = 0;
        for (int w = 0; w < 8; ++w)
            if (w < wid) off += wsum[w];
        suffix[255 - tid] = csum[255 - tid] + off;
    }
    __syncthreads();

    if (tid < 256) {
        const float W1 = 16.0f / HB1;
        int run = suffix[tid];
        for (int b = b0 + 15; b >= b0; --b) {
            int prev = run;
            run += hist[b];
            if (prev < RANK_HI && run >= RANK_HI)
                g_Thi[row] = b * W1 + 0.01f;
            if (prev < RANK_LO && run >= RANK_LO)
                g_Tlo[row] = fmaxf(0.0f, b * W1 - 0.01f);
        }
    }
}

// ----------------- K2: per-warp cp.async ring pass + finalize
__global__ void __launch_bounds__(256) k_main(const float* __restrict__ Xg,
                                              const float* __restrict__ Yg,
                                              float* out) {
    extern __shared__ float stg[];       // [WARPS][DSTG][256 floats], 64 KB
    __shared__ int h2[BINS2];
    __shared__ float ws[8];
    __shared__ int wc[8];
    __shared__ int wsum[8];
    __shared__ bool isLast;

    const int tid = threadIdx.x;
    const int lane = tid & 31, warp = tid >> 5;
    const int row = blockIdx.x >> 4;      // BLKROW=16 blocks per row
    const int chunk = blockIdx.x & (BLKROW - 1);

    for (int i = tid; i < BINS2; i += 256) h2[i] = 0;
    const float Tlo = g_Tlo[row];
    const float Thi = g_Thi[row];
    const float invw = (float)BINS2 / (Thi - Tlo);
    __syncthreads();

    // per-warp ring + global segment
    float* wring = stg + warp * RING_FLOATS;
    const size_t gw = (size_t)row * HW + (size_t)chunk * (WARPS * WPIX)
                    + (size_t)warp * WPIX;
    const uint32_t ring0 = smem_u32(wring) + (uint32_t)lane * 16u;

    // prologue: issue stages 0..DSTG-2 (7 committed groups)
#pragma unroll
    for (int t = 0; t < DSTG - 1; ++t) {
        uint32_t sa = ring0 + (uint32_t)t * (2 * STAGE_PIX * 4);
        CP_ASYNC16(sa, Xg + gw + t * STAGE_PIX + lane * 4);
        CP_ASYNC16(sa + STAGE_PIX * 4, Yg + gw + t * STAGE_PIX + lane * 4);
        CP_COMMIT();
    }

    float s = 0.0f;
    int c = 0;
#pragma unroll 1
    for (int t = 0; t < NIT; ++t) {
        // keep one group per iteration (empty groups in the tail) so the
        // wait immediate can stay constant: retired >= t+2 after WAIT6.
        const int tf = t + DSTG - 1;
        if (tf < NIT) {
            const int slot = tf & (DSTG - 1);
            uint32_t sa = ring0 + (uint32_t)slot * (2 * STAGE_PIX * 4);
            CP_ASYNC16(sa, Xg + gw + tf * STAGE_PIX + lane * 4);
            CP_ASYNC16(sa + STAGE_PIX * 4, Yg + gw + tf * STAGE_PIX + lane * 4);
        }
        CP_COMMIT();
        CP_WAIT6();   // oldest in-flight group (stage t) is complete

        const int st = t & (DSTG - 1);
        float4 xv = *(const float4*)(wring + st * (2 * STAGE_PIX) + lane * 4);
        float4 yv = *(const float4*)(wring + st * (2 * STAGE_PIX) + STAGE_PIX + lane * 4);
        float L[4];
        L[0] = bce(xv.x, yv.x);
        L[1] = bce(xv.y, yv.y);
        L[2] = bce(xv.z, yv.z);
        L[3] = bce(xv.w, yv.w);
#pragma unroll
        for (int j = 0; j < 4; ++j) {
            float Lv = L[j];
            bool hi = (Lv >= Thi);
            s += hi ? Lv : 0.0f;
            c += hi ? 1 : 0;
            if (!hi && Lv >= Tlo) {
                int b = (int)((Lv - Tlo) * invw);
                atomicAdd(&h2[min(BINS2 - 1, b)], 1);
            }
        }
    }
    __syncthreads();   // all warps done before h2 flush

    // flush fine histogram (skip empty bins)
    for (int i = tid; i < BINS2; i += 256) {
        int v = h2[i];
        if (v) atomicAdd(&g_cnt2[row][i], v);
    }

    // exact sum/count above Thi: warp + block reduction, 1 atomic pair/block
#pragma unroll
    for (int o = 16; o; o >>= 1) {
        s += __shfl_down_sync(0xffffffffu, s, o);
        c += __shfl_down_sync(0xffffffffu, c, o);
    }
    if (lane == 0) { ws[warp] = s; wc[warp] = c; }
    __syncthreads();
    if (tid == 0) {
        float S = 0.0f; int C = 0;
#pragma unroll
        for (int w = 0; w < 8; ++w) { S += ws[w]; C += wc[w]; }
        atomicAdd(&g_Shi[row], S);
        atomicAdd(&g_Chi[row], C);
    }

    // ---- last-block-per-row finalize ----
    __threadfence();
    __syncthreads();
    if (tid == 0) {
        unsigned int d = atomicAdd(&g_done[row], 1u);
        isLast = (d == BLKROW - 1u);
    }
    __syncthreads();
    if (!isLast) return;

    const int Chi = __ldcg(&g_Chi[row]);
    const float Shi = __ldcg(&g_Shi[row]);
    const float w2 = (Thi - Tlo) * (1.0f / (float)BINS2);

    const int b1 = BINS2 - 1 - 2 * tid;
    const int bq0 = BINS2 - 2 - 2 * tid;
    int c1 = __ldcg(&g_cnt2[row][b1]);
    int c0 = __ldcg(&g_cnt2[row][bq0]);
    int local = c1 + c0;

    int inc = local;
#pragma unroll
    for (int o = 1; o < 32; o <<= 1) {
        int u = __shfl_up_sync(0xffffffffu, inc, o);
        if (lane >= o) inc += u;
    }
    if (lane == 31) wsum[warp] = inc;
    __syncthreads();
    int off = 0, totalAll = 0;
#pragma unroll
    for (int w = 0; w < 8; ++w) {
        int t = wsum[w];
        if (w < warp) off += t;
        totalAll += t;
    }
    int excl = inc + off - local;

    float psum = 0.0f;
    int need = TOPK - Chi;
    if (need > 0) {
        int rem1 = need - excl;
        int take1 = min(max(rem1, 0), c1);
        int rem0 = rem1 - c1;
        int take0 = min(max(rem0, 0), c0);
        psum = (float)take1 * (Tlo + ((float)b1 + 0.5f) * w2)
             + (float)take0 * (Tlo + ((float)bq0 + 0.5f) * w2);
    }
#pragma unroll
    for (int o = 16; o; o >>= 1) psum += __shfl_down_sync(0xffffffffu, psum, o);
    if (lane == 0) ws[warp] = psum;
    __syncthreads();
    if (tid == 0) {
        float sum = 0.0f;
#pragma unroll
        for (int w = 0; w < 8; ++w) sum += ws[w];
        float rowsum;
        if (Chi >= TOPK) {
            rowsum = Shi * ((float)TOPK / (float)Chi);
        } else {
            int need2 = TOPK - Chi;
            if (totalAll < need2) sum += (float)(need2 - totalAll) * Tlo;
            rowsum = Shi + sum;
        }
        atomicAdd(out, rowsum * (1.0f / ((float)NB * (float)TOPK)));
    }
}

extern "C" void kernel_launch(void* const* d_in, const int* in_sizes, int n_in,
                              void* d_out, int out_size) {
    const float* X = (const float*)d_in[0];  // pred_logits
    const float* Y = (const float*)d_in[1];  // gts
    float* out = (float*)d_out;

    static bool attr_set = false;            // host-side config, not device state
    if (!attr_set) {
        cudaFuncSetAttribute(k_main, cudaFuncAttributeMaxDynamicSharedMemorySize,
                             DSMEM);
        attr_set = true;
    }

    k_sample<<<NB, 1024>>>((const float4*)X, (const float4*)Y, out);
    k_main<<<NB * BLKROW, 256, DSMEM>>>(X, Y, out);
}

// round 14
// speedup vs baseline: 1.2108x; 1.2108x over previous
#include <cuda_runtime.h>
#include <cuda_bf16.h>
#include <math.h>
#include <stdint.h>

// BootstrappedBCEWithLogitsLoss: mean of top-25% per-row BCE losses.
// B=64 rows of HW=262144 pixels; K = 65536 per row.
//
// Finding (R5-R13): achieved read bandwidth pins at ~4 TB/s for every load
// strategy tried -> environmental ceiling. k_main uses the measured-best
// config (R8: 2-stage double-buffered cp.async.bulk, 2048-px tiles, 32 blocks
// /row, 32KB static smem). This round trims k_sample: 8192-px sample (half
// the bytes) with ~9-sigma widened rank margins.
//
//  k_sample (1024 thr): zero scratch + per-row 8192-pixel sample ->
//            4096-bin smem histogram -> conservative bracket [Tlo,Thi].
//  k_main  (256 thr, 32 blocks/row, 4 tiles x 2048px, double-buffered TMA):
//            loss >= Thi: exact branchless sum/count.
//            loss in [Tlo,Thi): 512-bin smem histogram (~9% of pixels).
//            Last block per row finalizes via parallel suffix scan.

#define NB 64
#define HW 262144
#define TOPK 65536
#define SAMPLE 8192
#define HB1 4096
#define BINS2 512
#define BLKROW 32            // blocks per row in k_main
#define NTILE 4              // tiles per block
#define TILE_PIX 2048        // pixels per tile
#define TILE_BYTES (TILE_PIX * 4)
#define RANK_HI 1690   // 2048 - ~9 sigma (sigma ~ 39 ranks at n=8192)
#define RANK_LO 2410   // 2048 + ~9 sigma

__device__ float g_Tlo[NB];
__device__ float g_Thi[NB];
__device__ float g_Shi[NB];
__device__ int   g_Chi[NB];
__device__ int   g_cnt2[NB][BINS2];
__device__ unsigned int g_done[NB];

__device__ __forceinline__ float bce(float x, float y) {
    return fmaxf(x, 0.0f) - x * y + __logf(1.0f + __expf(-fabsf(x)));
}

__device__ __forceinline__ uint32_t smem_u32(const void* p) {
    return (uint32_t)__cvta_generic_to_shared(p);
}

__device__ __forceinline__ void mbar_wait(uint32_t mb, uint32_t parity) {
    uint32_t done2;
    do {
        asm volatile(
            "{\n\t.reg .pred p;\n\t"
            "mbarrier.try_wait.parity.acquire.cta.shared::cta.b64 p, [%1], %2, 0x989680;\n\t"
            "selp.b32 %0, 1, 0, p;\n\t}"
            : "=r"(done2) : "r"(mb), "r"(parity) : "memory");
    } while (!done2);
}

// ---------------------------------------------- K1: zero scratch + sample
__global__ void __launch_bounds__(1024) k_sample(const float4* __restrict__ X,
                                                 const float4* __restrict__ Y,
                                                 float* out) {
    __shared__ int hist[HB1];
    __shared__ int csum[256];
    __shared__ int suffix[256];
    __shared__ int wsum[8];
    const int tid = threadIdx.x;
    const int row = blockIdx.x;

    if (tid < BINS2) g_cnt2[row][tid] = 0;
    if (tid == 0) {
        g_Chi[row] = 0;
        g_Shi[row] = 0.0f;
        g_done[row] = 0;
        if (row == 0) out[0] = 0.0f;
    }

    for (int i = tid; i < HB1; i += 1024) hist[i] = 0;
    __syncthreads();

    // 2048 float4-pairs / 1024 threads = 2 per thread, front-batched.
    size_t base = (size_t)row * (HW / 4);
    {
        float4 xv[2], yv[2];
#pragma unroll
        for (int k = 0; k < 2; ++k) {
            int i = k * 1024 + tid;
            xv[k] = X[base + i];
            yv[k] = Y[base + i];
        }
#pragma unroll
        for (int k = 0; k < 2; ++k) {
            float L0 = bce(xv[k].x, yv[k].x);
            float L1 = bce(xv[k].y, yv[k].y);
            float L2 = bce(xv[k].z, yv[k].z);
            float L3 = bce(xv[k].w, yv[k].w);
            atomicAdd(&hist[min(HB1 - 1, max(0, (int)(L0 * 256.0f)))], 1);
            atomicAdd(&hist[min(HB1 - 1, max(0, (int)(L1 * 256.0f)))], 1);
            atomicAdd(&hist[min(HB1 - 1, max(0, (int)(L2 * 256.0f)))], 1);
            atomicAdd(&hist[min(HB1 - 1, max(0, (int)(L3 * 256.0f)))], 1);
        }
    }
    __syncthreads();

    const int b0 = tid * (HB1 / 256);  // only valid for tid<256
    if (tid < 256) {
        int lt = 0;
#pragma unroll
        for (int b = b0; b < b0 + 16; ++b) lt += hist[b];
        csum[tid] = lt;
    }
    __syncthreads();

    if (tid < 256) {
        const int lane = tid & 31, wid = tid >> 5;
        int v = csum[255 - tid];
        int inc = v;
#pragma unroll
        for (int o = 1; o < 32; o <<= 1) {
            int u = __shfl_up_sync(0xffffffffu, inc, o);
            if (lane >= o) inc += u;
        }
        if (lane == 31) wsum[wid] = inc;
        csum[255 - tid] = inc - v;
    }
    __syncthreads();
    if (tid < 256) {
        const int wid = tid >> 5;
        int off = 0;
        for (int w = 0; w < 8; ++w)
            if (w < wid) off += wsum[w];
        suffix[255 - tid] = csum[255 - tid] + off;
    }
    __syncthreads();

    if (tid < 256) {
        const float W1 = 16.0f / HB1;
        int run = suffix[tid];
        for (int b = b0 + 15; b >= b0; --b) {
            int prev = run;
            run += hist[b];
            if (prev < RANK_HI && run >= RANK_HI)
                g_Thi[row] = b * W1 + 0.01f;
            if (prev < RANK_LO && run >= RANK_LO)
                g_Tlo[row] = fmaxf(0.0f, b * W1 - 0.01f);
        }
    }
}

// ------------------ K2: double-buffered TMA pipeline (R8) + finalize
__global__ void __launch_bounds__(256) k_main(const float* __restrict__ Xg,
                                              const float* __restrict__ Yg,
                                              float* out) {
    __shared__ alignas(16) float sx[2][TILE_PIX];   // 2 x 8 KB
    __shared__ alignas(16) float sy[2][TILE_PIX];   // 2 x 8 KB
    __shared__ int h2[BINS2];
    __shared__ float ws[8];
    __shared__ int wc[8];
    __shared__ int wsum[8];
    __shared__ bool isLast;
    __shared__ alignas(8) unsigned long long mbar[2];

    const int tid = threadIdx.x;
    const int lane = tid & 31, warp = tid >> 5;
    const int row = blockIdx.x >> 5;      // BLKROW=32 blocks per row
    const int chunk = blockIdx.x & (BLKROW - 1);
    const uint32_t mb0 = smem_u32(&mbar[0]);
    const uint32_t mb1 = smem_u32(&mbar[1]);

    if (tid == 0) {
        asm volatile("mbarrier.init.shared.b64 [%0], 1;" :: "r"(mb0) : "memory");
        asm volatile("mbarrier.init.shared.b64 [%0], 1;" :: "r"(mb1) : "memory");
        asm volatile("fence.proxy.async.shared::cta;" ::: "memory");
    }
    for (int i = tid; i < BINS2; i += 256) h2[i] = 0;
    const float Tlo = g_Tlo[row];
    const float Thi = g_Thi[row];
    const float invw = (float)BINS2 / (Thi - Tlo);
    __syncthreads();

    const size_t base = (size_t)row * HW + (size_t)chunk * (NTILE * TILE_PIX);

    // prologue: kick tile 0 into stage 0
    if (tid == 0) {
        asm volatile("mbarrier.arrive.expect_tx.shared.b64 _, [%0], %1;"
                     :: "r"(mb0), "r"(2 * TILE_BYTES) : "memory");
        asm volatile("cp.async.bulk.shared::cta.global.mbarrier::complete_tx::bytes "
                     "[%0], [%1], %2, [%3];"
                     :: "r"(smem_u32(sx[0])), "l"(Xg + base), "r"(TILE_BYTES), "r"(mb0)
                     : "memory");
        asm volatile("cp.async.bulk.shared::cta.global.mbarrier::complete_tx::bytes "
                     "[%0], [%1], %2, [%3];"
                     :: "r"(smem_u32(sy[0])), "l"(Yg + base), "r"(TILE_BYTES), "r"(mb0)
                     : "memory");
    }

    float s = 0.0f;
    int c = 0;
#pragma unroll
    for (int t = 0; t < NTILE; ++t) {
        const int st = t & 1;
        const uint32_t mb = st ? mb1 : mb0;
        mbar_wait(mb, (t >> 1) & 1);

        // issue tile t+1 into the other stage BEFORE computing tile t.
        if (tid == 0 && t + 1 < NTILE) {
            const int ns = (t + 1) & 1;
            const uint32_t nmb = ns ? mb1 : mb0;
            const size_t off = base + (size_t)(t + 1) * TILE_PIX;
            asm volatile("mbarrier.arrive.expect_tx.shared.b64 _, [%0], %1;"
                         :: "r"(nmb), "r"(2 * TILE_BYTES) : "memory");
            asm volatile("cp.async.bulk.shared::cta.global.mbarrier::complete_tx::bytes "
                         "[%0], [%1], %2, [%3];"
                         :: "r"(smem_u32(sx[ns])), "l"(Xg + off), "r"(TILE_BYTES), "r"(nmb)
                         : "memory");
            asm volatile("cp.async.bulk.shared::cta.global.mbarrier::complete_tx::bytes "
                         "[%0], [%1], %2, [%3];"
                         :: "r"(smem_u32(sy[ns])), "l"(Yg + off), "r"(TILE_BYTES), "r"(nmb)
                         : "memory");
        }

        const float4* bx = (const float4*)sx[st];
        const float4* by = (const float4*)sy[st];
#pragma unroll
        for (int k = 0; k < 2; ++k) {
            float4 xv = bx[k * 256 + tid];
            float4 yv = by[k * 256 + tid];
            float L[4];
            L[0] = bce(xv.x, yv.x);
            L[1] = bce(xv.y, yv.y);
            L[2] = bce(xv.z, yv.z);
            L[3] = bce(xv.w, yv.w);
#pragma unroll
            for (int j = 0; j < 4; ++j) {
                float Lv = L[j];
                bool hi = (Lv >= Thi);
                s += hi ? Lv : 0.0f;
                c += hi ? 1 : 0;
                if (!hi && Lv >= Tlo) {
                    int b = (int)((Lv - Tlo) * invw);
                    atomicAdd(&h2[min(BINS2 - 1, b)], 1);
                }
            }
        }
        __syncthreads();   // stage st free for tile t+2; compute(t) done
    }

    // flush fine histogram (skip empty bins)
    for (int i = tid; i < BINS2; i += 256) {
        int v = h2[i];
        if (v) atomicAdd(&g_cnt2[row][i], v);
    }

    // exact sum/count above Thi: warp + block reduction, 1 atomic pair/block
#pragma unroll
    for (int o = 16; o; o >>= 1) {
        s += __shfl_down_sync(0xffffffffu, s, o);
        c += __shfl_down_sync(0xffffffffu, c, o);
    }
    if (lane == 0) { ws[warp] = s; wc[warp] = c; }
    __syncthreads();
    if (tid == 0) {
        float S = 0.0f; int C = 0;
#pragma unroll
        for (int w = 0; w < 8; ++w) { S += ws[w]; C += wc[w]; }
        atomicAdd(&g_Shi[row], S);
        atomicAdd(&g_Chi[row], C);
    }

    // ---- last-block-per-row finalize ----
    __threadfence();
    __syncthreads();
    if (tid == 0) {
        unsigned int d = atomicAdd(&g_done[row], 1u);
        isLast = (d == BLKROW - 1u);
    }
    __syncthreads();
    if (!isLast) return;

    const int Chi = __ldcg(&g_Chi[row]);
    const float Shi = __ldcg(&g_Shi[row]);
    const float w2 = (Thi - Tlo) * (1.0f / (float)BINS2);

    const int b1 = BINS2 - 1 - 2 * tid;
    const int bq0 = BINS2 - 2 - 2 * tid;
    int c1 = __ldcg(&g_cnt2[row][b1]);
    int c0 = __ldcg(&g_cnt2[row][bq0]);
    int local = c1 + c0;

    int inc = local;
#pragma unroll
    for (int o = 1; o < 32; o <<= 1) {
        int u = __shfl_up_sync(0xffffffffu, inc, o);
        if (lane >= o) inc += u;
    }
    if (lane == 31) wsum[warp] = inc;
    __syncthreads();
    int off = 0, totalAll = 0;
#pragma unroll
    for (int w = 0; w < 8; ++w) {
        int t = wsum[w];
        if (w < warp) off += t;
        totalAll += t;
    }
    int excl = inc + off - local;

    float psum = 0.0f;
    int need = TOPK - Chi;
    if (need > 0) {
        int rem1 = need - excl;
        int take1 = min(max(rem1, 0), c1);
        int rem0 = rem1 - c1;
        int take0 = min(max(rem0, 0), c0);
        psum = (float)take1 * (Tlo + ((float)b1 + 0.5f) * w2)
             + (float)take0 * (Tlo + ((float)bq0 + 0.5f) * w2);
    }
#pragma unroll
    for (int o = 16; o; o >>= 1) psum += __shfl_down_sync(0xffffffffu, psum, o);
    if (lane == 0) ws[warp] = psum;
    __syncthreads();
    if (tid == 0) {
        float sum = 0.0f;
#pragma unroll
        for (int w = 0; w < 8; ++w) sum += ws[w];
        float rowsum;
        if (Chi >= TOPK) {
            rowsum = Shi * ((float)TOPK / (float)Chi);
        } else {
            int need2 = TOPK - Chi;
            if (totalAll < need2) sum += (float)(need2 - totalAll) * Tlo;
            rowsum = Shi + sum;
        }
        atomicAdd(out, rowsum * (1.0f / ((float)NB * (float)TOPK)));
    }
}

extern "C" void kernel_launch(void* const* d_in, const int* in_sizes, int n_in,
                              void* d_out, int out_size) {
    const float* X = (const float*)d_in[0];  // pred_logits
    const float* Y = (const float*)d_in[1];  // gts
    float* out = (float*)d_out;

    k_sample<<<NB, 1024>>>((const float4*)X, (const float4*)Y, out);
    k_main<<<NB * BLKROW, 256>>>(X, Y, out);
}